// round 15
// baseline (speedup 1.0000x reference)
#include <cuda_runtime.h>
#include <math.h>
#include <math_constants.h>

#define NPIX  32768      // 128*256 pixels
#define NE    128
#define NS    2048
#define NTOT  (16*128*2048)
#define CNT   4194304.0  // per-channel BN count = NPIX*NE

typedef unsigned long long u64;

// float2-index skew: stride-8 thread bases -> stride 9 (conflict-free wavefronts)
#define XA0(c) ((c) + ((c) >> 3))

// ---------------- scratch ----------------
__device__ float    g_iT[NS * NE];           // event-0 I, transposed [s][e]
__device__ float    g_qT[NS * NE];           // event-0 Q, transposed [s][e]
__device__ float    g_actA[NPIX * 8 * NE];
__device__ float    g_actB[NPIX * 8 * NE];
__device__ float    g_wraw[NPIX * NE];
__device__ float    g_sumI[NPIX];
__device__ float    g_sumQ[NPIX];
__device__ float    g_ydb [NPIX];
__device__ unsigned g_maxsq;
__device__ unsigned g_maxydb;
__device__ double   g_stats[4][16];   // per-layer [sum(8) | sumsq(8)]

__device__ __forceinline__ unsigned ford(float f) {
    unsigned u = __float_as_uint(f);
    return (u & 0x80000000u) ? ~u : (u | 0x80000000u);
}

// packed fp32x2 helpers (lanes = two pixels)
__device__ __forceinline__ u64 ffma2(u64 a, u64 b, u64 c) {
    u64 d;
    asm("fma.rn.f32x2 %0,%1,%2,%3;" : "=l"(d) : "l"(a), "l"(b), "l"(c));
    return d;
}
__device__ __forceinline__ u64 pack2(float lo, float hi) {
    u64 d;
    asm("mov.b64 %0,{%1,%2};" : "=l"(d) : "f"(lo), "f"(hi));
    return d;
}
__device__ __forceinline__ void unpack2(u64 a, float& lo, float& hi) {
    asm("mov.b64 {%0,%1},%2;" : "=f"(lo), "=f"(hi) : "l"(a));
}

// transpose event-0 I/Q: [e][s] -> [s][e]; also does global init (runs first in stream)
__global__ void k_tr(const float* __restrict__ id, const float* __restrict__ qd) {
    __shared__ float ti[32][33], tq[32][33];
    int e0 = blockIdx.x * 32, s0 = blockIdx.y * 32;
    int tx = threadIdx.x, ty = threadIdx.y;
    if (blockIdx.x == 0 && blockIdx.y == 0 && ty == 0) {
        int t = tx;
        if (t < 32) { ((double*)g_stats)[t] = 0.0; ((double*)g_stats)[t + 32] = 0.0; }
        if (t == 0) { g_maxsq = 0u; g_maxydb = 0u; }
    }
    ti[ty][tx] = id[(e0 + ty) * NS + s0 + tx];
    tq[ty][tx] = qd[(e0 + ty) * NS + s0 + tx];
    __syncthreads();
    g_iT[(s0 + ty) * NE + e0 + tx] = ti[tx][ty];
    g_qT[(s0 + ty) * NE + e0 + tx] = tq[tx][ty];
}

// max of i^2+q^2: one pass, 4 independent float4-pairs per thread (MLP=8)
// launched with exactly (NTOT/16)/256 = 1024 blocks of 256 threads
__global__ void __launch_bounds__(256) k_nrm(const float* __restrict__ id,
                                             const float* __restrict__ qd) {
    const float4* i4 = (const float4*)id;
    const float4* q4 = (const float4*)qd;
    const int S = (NTOT / 4) / 4;   // 262144
    int i = blockIdx.x * blockDim.x + threadIdx.x;   // 0..262143
    float4 a0 = i4[i], a1 = i4[i + S], a2 = i4[i + 2 * S], a3 = i4[i + 3 * S];
    float4 b0 = q4[i], b1 = q4[i + S], b2 = q4[i + 2 * S], b3 = q4[i + 3 * S];
    float m = 0.f;
    m = fmaxf(m, a0.x * a0.x + b0.x * b0.x); m = fmaxf(m, a0.y * a0.y + b0.y * b0.y);
    m = fmaxf(m, a0.z * a0.z + b0.z * b0.z); m = fmaxf(m, a0.w * a0.w + b0.w * b0.w);
    m = fmaxf(m, a1.x * a1.x + b1.x * b1.x); m = fmaxf(m, a1.y * a1.y + b1.y * b1.y);
    m = fmaxf(m, a1.z * a1.z + b1.z * b1.z); m = fmaxf(m, a1.w * a1.w + b1.w * b1.w);
    m = fmaxf(m, a2.x * a2.x + b2.x * b2.x); m = fmaxf(m, a2.y * a2.y + b2.y * b2.y);
    m = fmaxf(m, a2.z * a2.z + b2.z * b2.z); m = fmaxf(m, a2.w * a2.w + b2.w * b2.w);
    m = fmaxf(m, a3.x * a3.x + b3.x * b3.x); m = fmaxf(m, a3.y * a3.y + b3.y * b3.y);
    m = fmaxf(m, a3.z * a3.z + b3.z * b3.z); m = fmaxf(m, a3.w * a3.w + b3.w * b3.w);
    for (int off = 16; off; off >>= 1) m = fmaxf(m, __shfl_down_sync(0xffffffffu, m, off));
    __shared__ float sm[8];
    int lane = threadIdx.x & 31, w = threadIdx.x >> 5;
    if (lane == 0) sm[w] = m;
    __syncthreads();
    if (threadIdx.x == 0) {
        float mm = sm[0];
        for (int i2 = 1; i2 < 8; i2++) mm = fmaxf(mm, sm[i2]);
        atomicMax(&g_maxsq, __float_as_uint(mm));
    }
}

// ============ fused beamform + conv1 (2->8, K=65, pad=32); dual-pixel f32x2 ============
__global__ void __launch_bounds__(256, 4) k_bfconv1(
        const float* __restrict__ angles, const float* __restrict__ ele_pos,
        const float* __restrict__ time_zero, const float* __restrict__ grid,
        const float* __restrict__ w, const float* __restrict__ b) {
    __shared__ float2 swd[1040];        // weights duplicated (w,w), [co][ci][k]
    __shared__ float2 sxp[2][2][220];   // (p0,p1) pairs, skewed; XA0(191)=214
    __shared__ float  sred[16];
    __shared__ float2 sIw[2][4], sQw[2][4];
    int tid = threadIdx.x;
    int pbase = blockIdx.x * 4;

    for (int i = tid; i < 1040; i += 256) { float v = w[i]; swd[i] = make_float2(v, v); }
    if (tid < 16) sred[tid] = 0.f;
    {
        int i = tid;
        int h  = i & 63;
        int c  = (i >> 6) & 1;
        int pp = i >> 7;
        int x  = (h < 32) ? h : (128 + h);
        sxp[pp][c][XA0(x)] = make_float2(0.f, 0.f);
    }
    __syncthreads();

    {
        int pp = tid >> 7, e = tid & 127;
        int p0 = pbase + 2 * pp, p1 = p0 + 1;
        float ang = angles[0];
        float sA, cA;
        sincosf(ang, &sA, &cA);
        float tanA = tanf(ang);
        float tz = time_zero[0];
        float ex  = ele_pos[e * 3];
        float ex0 = ele_pos[0];
        float exL = ele_pos[(NE - 1) * 3];

        float x0 = grid[p0 * 3 + 0], z0 = grid[p0 * 3 + 2];
        float x1 = grid[p1 * 3 + 0], z1 = grid[p1 * 3 + 2];

        const float FSC = (float)(20832000.0 / 1540.0);
        float txdel0 = (x0 * sA + z0 * cA + tz * 1540.0f) * FSC;
        float vx0 = x0 - ex;
        float dist0 = sqrtf(vx0 * vx0 + z0 * z0);
        float delays0 = txdel0 + dist0 * FSC;
        float d00 = floorf(delays0);
        float frac0 = delays0 - d00;
        int i00 = (int)d00;
        float txdel1 = (x1 * sA + z1 * cA + tz * 1540.0f) * FSC;
        float vx1 = x1 - ex;
        float dist1 = sqrtf(vx1 * vx1 + z1 * z1);
        float delays1 = txdel1 + dist1 * FSC;
        float d01 = floorf(delays1);
        float frac1 = delays1 - d01;
        int i01 = (int)d01;

        bool a0 = (i00 >= 0 && i00 < NS), a1 = (i00 + 1 >= 0 && i00 + 1 < NS);
        bool b0 = (i01 >= 0 && i01 < NS), b1 = (i01 + 1 >= 0 && i01 + 1 < NS);
        float iv00 = a0 ? g_iT[i00 * NE + e]       : 0.f;
        float iv01 = a1 ? g_iT[(i00 + 1) * NE + e] : 0.f;
        float qv00 = a0 ? g_qT[i00 * NE + e]       : 0.f;
        float qv01 = a1 ? g_qT[(i00 + 1) * NE + e] : 0.f;
        float iv10 = b0 ? g_iT[i01 * NE + e]       : 0.f;
        float iv11 = b1 ? g_iT[(i01 + 1) * NE + e] : 0.f;
        float qv10 = b0 ? g_qT[i01 * NE + e]       : 0.f;
        float qv11 = b1 ? g_qT[(i01 + 1) * NE + e] : 0.f;

        float invn = rsqrtf(__uint_as_float(g_maxsq));
        float ifoc0 = (iv00 * (1.f - frac0) + iv01 * frac0) * invn;
        float qfoc0 = (qv00 * (1.f - frac0) + qv01 * frac0) * invn;
        float ifoc1 = (iv10 * (1.f - frac1) + iv11 * frac1) * invn;
        float qfoc1 = (qv10 * (1.f - frac1) + qv11 * frac1) * invn;

        float tshift0 = delays0 / 20832000.0f - (z0 * 2.0f) / 1540.0f;
        float theta0 = (float)(2.0 * CUDART_PI * 5208000.0) * tshift0;
        float st0, ct0;
        sincosf(theta0, &st0, &ct0);
        float tshift1 = delays1 / 20832000.0f - (z1 * 2.0f) / 1540.0f;
        float theta1 = (float)(2.0 * CUDART_PI * 5208000.0) * tshift1;
        float st1, ct1;
        sincosf(theta1, &st1, &ct1);

        float ir0 = ifoc0 * ct0 - qfoc0 * st0;
        float qr0 = qfoc0 * ct0 + ifoc0 * st0;
        float ir1 = ifoc1 * ct1 - qfoc1 * st1;
        float qr1 = qfoc1 * ct1 + ifoc1 * st1;

        {
            float avx = fabsf(vx0);
            bool mrx = (fabsf(z0) > avx) || (avx <= 0.001f) ||
                       ((vx0 >= 0.001f)  && (x0 <= ex0)) ||
                       ((vx0 <= -0.001f) && (x0 >= exL));
            float xp = x0 - z0 * tanA;
            bool mtx = (xp >= ex0 * 1.2f) && (xp <= exL * 1.2f);
            if (!(mrx && mtx)) { ir0 = 0.f; qr0 = 0.f; }
        }
        {
            float avx = fabsf(vx1);
            bool mrx = (fabsf(z1) > avx) || (avx <= 0.001f) ||
                       ((vx1 >= 0.001f)  && (x1 <= ex0)) ||
                       ((vx1 <= -0.001f) && (x1 >= exL));
            float xp = x1 - z1 * tanA;
            bool mtx = (xp >= ex0 * 1.2f) && (xp <= exL * 1.2f);
            if (!(mrx && mtx)) { ir1 = 0.f; qr1 = 0.f; }
        }

        sxp[pp][0][XA0(e + 32)] = make_float2(ir0, ir1);
        sxp[pp][1][XA0(e + 32)] = make_float2(qr0, qr1);

        float a0s = ir0, a1s = ir1, b0s = qr0, b1s = qr1;
        for (int off = 16; off; off >>= 1) {
            a0s += __shfl_down_sync(0xffffffffu, a0s, off);
            a1s += __shfl_down_sync(0xffffffffu, a1s, off);
            b0s += __shfl_down_sync(0xffffffffu, b0s, off);
            b1s += __shfl_down_sync(0xffffffffu, b1s, off);
        }
        int lane = e & 31, wix = e >> 5;
        if (lane == 0) { sIw[pp][wix] = make_float2(a0s, a1s); sQw[pp][wix] = make_float2(b0s, b1s); }
    }
    __syncthreads();
    if (tid < 2) {
        int pp = tid;
        int p0 = pbase + 2 * pp;
        g_sumI[p0]     = sIw[pp][0].x + sIw[pp][1].x + sIw[pp][2].x + sIw[pp][3].x;
        g_sumI[p0 + 1] = sIw[pp][0].y + sIw[pp][1].y + sIw[pp][2].y + sIw[pp][3].y;
        g_sumQ[p0]     = sQw[pp][0].x + sQw[pp][1].x + sQw[pp][2].x + sQw[pp][3].x;
        g_sumQ[p0 + 1] = sQw[pp][0].y + sQw[pp][1].y + sQw[pp][2].y + sQw[pp][3].y;
    }

    int pp = tid >> 7, t = tid & 127, co = t >> 4, g = t & 15;  // e0 = 8g
    float bias = b[co];
    u64 acc[8];
#pragma unroll
    for (int j = 0; j < 8; j++) acc[j] = pack2(bias, bias);

#pragma unroll
    for (int ci = 0; ci < 2; ci++) {
        const u64* wp  = (const u64*)&swd[(co * 2 + ci) * 65];
        const u64* spg = ((const u64*)&sxp[pp][ci][0]) + 9 * g;  // XA(e0)=9g
        u64 pe[15];
#pragma unroll
        for (int i = 0; i < 15; i++) pe[i] = spg[XA0(i)];
#pragma unroll
        for (int kb = 0; kb < 64; kb += 8) {
#pragma unroll
            for (int k = 0; k < 8; k++) {
                u64 wk = wp[kb + k];
#pragma unroll
                for (int j = 0; j < 8; j++) acc[j] = ffma2(wk, pe[k + j], acc[j]);
            }
#pragma unroll
            for (int i = 0; i < 7; i++) pe[i] = pe[i + 8];
            if (kb < 56) {
#pragma unroll
                for (int i = 7; i < 15; i++) pe[i] = spg[XA0(kb + 8 + i)];
            } else {
                pe[7] = spg[XA0(71)];
            }
        }
        u64 wl = wp[64];
#pragma unroll
        for (int j = 0; j < 8; j++) acc[j] = ffma2(wl, pe[j], acc[j]);
    }

    int p0 = pbase + pp * 2;
    float f0[8], f1[8];
    float s = 0.f, ss = 0.f;
#pragma unroll
    for (int j = 0; j < 8; j++) {
        unpack2(acc[j], f0[j], f1[j]);
        s += f0[j] + f1[j];
        ss += f0[j] * f0[j] + f1[j] * f1[j];
    }
    float4* o0 = (float4*)&g_actA[p0 * 1024 + co * 128 + g * 8];
    float4* o1 = (float4*)&g_actA[(p0 + 1) * 1024 + co * 128 + g * 8];
    o0[0] = make_float4(f0[0], f0[1], f0[2], f0[3]);
    o0[1] = make_float4(f0[4], f0[5], f0[6], f0[7]);
    o1[0] = make_float4(f1[0], f1[1], f1[2], f1[3]);
    o1[1] = make_float4(f1[4], f1[5], f1[6], f1[7]);
    for (int off = 8; off; off >>= 1) {
        s  += __shfl_down_sync(0xffffffffu, s,  off, 16);
        ss += __shfl_down_sync(0xffffffffu, ss, off, 16);
    }
    if (g == 0) { atomicAdd(&sred[co], s); atomicAdd(&sred[8 + co], ss); }
    __syncthreads();
    if (tid < 8) {
        atomicAdd(&g_stats[0][tid],     (double)sred[tid]);
        atomicAdd(&g_stats[0][8 + tid], (double)sred[8 + tid]);
    }
}

// ====== conv2/3: BN(prev)+relu on load; 8->8, K=15; dual-pixel f32x2; 2 co/thread ======
__global__ void __launch_bounds__(256, 3) k_conv23(const float* __restrict__ w,
                                                   const float* __restrict__ b,
                                                   const float* __restrict__ gam,
                                                   const float* __restrict__ bet,
                                                   int layer, int flip) {
    __shared__ float2 swd[960];         // duplicated weights [co][ci][k]
    __shared__ float2 sxp[4][8][164];   // 4 pixel-pairs; XA0(141)=158
    __shared__ float  ssc[8], ssh[8];
    __shared__ float  sred[16];
    const float* in  = flip ? g_actB : g_actA;
    float*       out = flip ? g_actA : g_actB;

    int tid = threadIdx.x;
    int pbase = blockIdx.x * 8;         // 8 pixels per block

    for (int i = tid; i < 960; i += 256) { float v = w[i]; swd[i] = make_float2(v, v); }
    if (tid < 8) {
        double mu  = g_stats[layer - 1][tid] / CNT;
        double var = g_stats[layer - 1][8 + tid] / CNT - mu * mu;
        float sc = (float)((double)gam[tid] / sqrt(var + 1e-5));
        ssc[tid] = sc;
        ssh[tid] = bet[tid] - (float)mu * sc;
    }
    if (tid < 16) sred[tid] = 0.f;
    for (int i = tid; i < 448; i += 256) {
        int h  = i % 14;
        int c  = (i / 14) & 7;
        int pp = i / 112;
        int x  = (h < 7) ? h : (128 + h);
        sxp[pp][c][XA0(x)] = make_float2(0.f, 0.f);
    }
    __syncthreads();

#pragma unroll
    for (int it = 0; it < 4; it++) {
        int i  = tid + it * 256;
        int e4 = i & 31;
        int c  = (i >> 5) & 7;
        int pp = i >> 8;
        int p0 = pbase + pp * 2;
        float sc = ssc[c], sh = ssh[c];
        float4 a = *(const float4*)&in[p0 * 1024 + c * 128 + e4 * 4];
        float4 d = *(const float4*)&in[(p0 + 1) * 1024 + c * 128 + e4 * 4];
        int xb = e4 * 4 + 7;
        sxp[pp][c][XA0(xb + 0)] = make_float2(fmaxf(fmaf(a.x, sc, sh), 0.f), fmaxf(fmaf(d.x, sc, sh), 0.f));
        sxp[pp][c][XA0(xb + 1)] = make_float2(fmaxf(fmaf(a.y, sc, sh), 0.f), fmaxf(fmaf(d.y, sc, sh), 0.f));
        sxp[pp][c][XA0(xb + 2)] = make_float2(fmaxf(fmaf(a.z, sc, sh), 0.f), fmaxf(fmaf(d.z, sc, sh), 0.f));
        sxp[pp][c][XA0(xb + 3)] = make_float2(fmaxf(fmaf(a.w, sc, sh), 0.f), fmaxf(fmaf(d.w, sc, sh), 0.f));
    }
    __syncthreads();

    int pp = tid >> 6, cop = (tid >> 4) & 3, g = tid & 15;
    int co0 = 2 * cop, co1 = 2 * cop + 1;
    u64 acc0[8], acc1[8];
    {
        float b0v = b[co0], b1v = b[co1];
#pragma unroll
        for (int j = 0; j < 8; j++) { acc0[j] = pack2(b0v, b0v); acc1[j] = pack2(b1v, b1v); }
    }

#pragma unroll
    for (int ci = 0; ci < 8; ci++) {
        const u64* wp0 = (const u64*)&swd[(co0 * 8 + ci) * 15];
        const u64* wp1 = (const u64*)&swd[(co1 * 8 + ci) * 15];
        const u64* spg = ((const u64*)&sxp[pp][ci][0]) + 9 * g;
        u64 pe[15];
#pragma unroll
        for (int i = 0; i < 15; i++) pe[i] = spg[XA0(i)];
#pragma unroll
        for (int k = 0; k < 8; k++) {
            u64 w0 = wp0[k], w1 = wp1[k];
#pragma unroll
            for (int j = 0; j < 8; j++) acc0[j] = ffma2(w0, pe[k + j], acc0[j]);
#pragma unroll
            for (int j = 0; j < 8; j++) acc1[j] = ffma2(w1, pe[k + j], acc1[j]);
        }
#pragma unroll
        for (int i = 0; i < 7; i++) pe[i] = pe[i + 8];
#pragma unroll
        for (int i = 7; i < 14; i++) pe[i] = spg[XA0(i + 8)];
#pragma unroll
        for (int k = 8; k < 15; k++) {
            u64 w0 = wp0[k], w1 = wp1[k];
#pragma unroll
            for (int j = 0; j < 8; j++) acc0[j] = ffma2(w0, pe[k - 8 + j], acc0[j]);
#pragma unroll
            for (int j = 0; j < 8; j++) acc1[j] = ffma2(w1, pe[k - 8 + j], acc1[j]);
        }
    }

    int p0 = pbase + pp * 2;
    float f0[8], f1[8], h0[8], h1[8];
    float s0 = 0.f, ss0 = 0.f, s1 = 0.f, ss1 = 0.f;
#pragma unroll
    for (int j = 0; j < 8; j++) {
        unpack2(acc0[j], f0[j], f1[j]);
        unpack2(acc1[j], h0[j], h1[j]);
        s0 += f0[j] + f1[j];  ss0 += f0[j] * f0[j] + f1[j] * f1[j];
        s1 += h0[j] + h1[j];  ss1 += h0[j] * h0[j] + h1[j] * h1[j];
    }
    {
        float4* o = (float4*)&out[p0 * 1024 + co0 * 128 + g * 8];
        o[0] = make_float4(f0[0], f0[1], f0[2], f0[3]);
        o[1] = make_float4(f0[4], f0[5], f0[6], f0[7]);
        o = (float4*)&out[(p0 + 1) * 1024 + co0 * 128 + g * 8];
        o[0] = make_float4(f1[0], f1[1], f1[2], f1[3]);
        o[1] = make_float4(f1[4], f1[5], f1[6], f1[7]);
        o = (float4*)&out[p0 * 1024 + co1 * 128 + g * 8];
        o[0] = make_float4(h0[0], h0[1], h0[2], h0[3]);
        o[1] = make_float4(h0[4], h0[5], h0[6], h0[7]);
        o = (float4*)&out[(p0 + 1) * 1024 + co1 * 128 + g * 8];
        o[0] = make_float4(h1[0], h1[1], h1[2], h1[3]);
        o[1] = make_float4(h1[4], h1[5], h1[6], h1[7]);
    }
    for (int off = 8; off; off >>= 1) {
        s0  += __shfl_down_sync(0xffffffffu, s0,  off, 16);
        ss0 += __shfl_down_sync(0xffffffffu, ss0, off, 16);
        s1  += __shfl_down_sync(0xffffffffu, s1,  off, 16);
        ss1 += __shfl_down_sync(0xffffffffu, ss1, off, 16);
    }
    if (g == 0) {
        atomicAdd(&sred[co0], s0); atomicAdd(&sred[8 + co0], ss0);
        atomicAdd(&sred[co1], s1); atomicAdd(&sred[8 + co1], ss1);
    }
    __syncthreads();
    if (tid < 8) {
        atomicAdd(&g_stats[layer][tid],     (double)sred[tid]);
        atomicAdd(&g_stats[layer][8 + tid], (double)sred[8 + tid]);
    }
}

// ---- conv4: BN3+relu fused; 8->1, K=3, pad=1; 8 pixels / 1024 threads ----
__global__ void __launch_bounds__(1024) k_conv4(const float* __restrict__ w,
                                                const float* __restrict__ b,
                                                const float* __restrict__ gam,
                                                const float* __restrict__ bet) {
    __shared__ float sw[24];
    __shared__ float ssc[8], ssh[8];
    __shared__ float sx[8][8][130];
    __shared__ float sred[64];
    int tid = threadIdx.x;
    int pbase = blockIdx.x * 8;

    if (tid < 24) sw[tid] = w[tid];
    if (tid < 8) {
        double mu  = g_stats[2][tid] / CNT;
        double var = g_stats[2][8 + tid] / CNT - mu * mu;
        float sc = (float)((double)gam[tid] / sqrt(var + 1e-5));
        ssc[tid] = sc;
        ssh[tid] = bet[tid] - (float)mu * sc;
    }
    if (tid >= 896) {   // halo: 8lp x 8c x 2 = 128 entries, disjoint thread group
        int i  = tid - 896;
        int lp = i >> 4;
        int c  = (i >> 1) & 7;
        int xi = (i & 1) ? 129 : 0;
        sx[lp][c][xi] = 0.f;
    }
    __syncthreads();

    // 8px x 8c x 32 f4 = 2048 loads over 1024 threads, 2 iters (both LDGs batched)
#pragma unroll
    for (int it = 0; it < 2; it++) {
        int i  = tid + it * 1024;
        int e4 = i & 31;
        int c  = (i >> 5) & 7;
        int lp = i >> 8;
        float sc = ssc[c], sh = ssh[c];
        float4 a = *(const float4*)&g_actA[(pbase + lp) * 1024 + c * 128 + e4 * 4];
        int xb = e4 * 4 + 1;
        sx[lp][c][xb + 0] = fmaxf(fmaf(a.x, sc, sh), 0.f);
        sx[lp][c][xb + 1] = fmaxf(fmaf(a.y, sc, sh), 0.f);
        sx[lp][c][xb + 2] = fmaxf(fmaf(a.z, sc, sh), 0.f);
        sx[lp][c][xb + 3] = fmaxf(fmaf(a.w, sc, sh), 0.f);
    }
    __syncthreads();

    int lp = tid >> 7, e = tid & 127;
    float acc = b[0];
#pragma unroll
    for (int ci = 0; ci < 8; ci++)
#pragma unroll
        for (int k = 0; k < 3; k++)
            acc = fmaf(sw[ci * 3 + k], sx[lp][ci][e + k], acc);

    g_wraw[(pbase + lp) * 128 + e] = acc;

    float s = acc, ss = acc * acc;
    for (int off = 16; off; off >>= 1) {
        s  += __shfl_down_sync(0xffffffffu, s,  off);
        ss += __shfl_down_sync(0xffffffffu, ss, off);
    }
    int lane = tid & 31, wix = tid >> 5;
    if (lane == 0) { sred[wix] = s; sred[32 + wix] = ss; }
    __syncthreads();
    if (tid == 0) {
        float S = 0.f, SS = 0.f;
        for (int i = 0; i < 32; i++) { S += sred[i]; SS += sred[32 + i]; }
        atomicAdd(&g_stats[3][0], (double)S);
        atomicAdd(&g_stats[3][1], (double)SS);
    }
}

// ---- BN4+relu+weight-sum+compound+dB + fused global max; 4 pixels / 512 threads ----
__global__ void __launch_bounds__(512) k_final(const float* __restrict__ gam,
                                               const float* __restrict__ bet) {
    int tid = threadIdx.x;
    int lp = tid >> 7, e = tid & 127;
    int p = blockIdx.x * 4 + lp;
    double mu  = g_stats[3][0] / CNT;
    double var = g_stats[3][1] / CNT - mu * mu;
    float sc = (float)((double)gam[0] / sqrt(var + 1e-5));
    float sh = bet[0] - (float)mu * sc;
    float wv = fmaxf(fmaf(g_wraw[p * 128 + e], sc, sh), 0.f);
    for (int off = 16; off; off >>= 1) wv += __shfl_down_sync(0xffffffffu, wv, off);
    __shared__ float sm[4][4];
    __shared__ unsigned smax;
    int lane = e & 31, w = e >> 5;
    if (tid == 0) smax = 0u;
    if (lane == 0) sm[lp][w] = wv;
    __syncthreads();
    if (e == 0) {
        float sW = sm[lp][0] + sm[lp][1] + sm[lp][2] + sm[lp][3];
        float cI = sW * g_sumI[p] * (1.0f / 128.0f);
        float cQ = sW * g_sumQ[p] * (1.0f / 128.0f);
        float mag = sqrtf(cI * cI + cQ * cQ);
        float y = 20.0f * log10f(mag + 1e-20f);
        g_ydb[p] = y;
        atomicMax(&smax, ford(y));
    }
    __syncthreads();
    if (tid == 0) atomicMax(&g_maxydb, smax);
}

__global__ void k_sub(float* __restrict__ out) {
    int i = blockIdx.x * blockDim.x + threadIdx.x;
    unsigned u = g_maxydb;
    float mx = (u & 0x80000000u) ? __uint_as_float(u & 0x7fffffffu) : __uint_as_float(~u);
    if (i < NPIX) out[i] = g_ydb[i] - mx;
}

extern "C" void kernel_launch(void* const* d_in, const int* in_sizes, int n_in,
                              void* d_out, int out_size) {
    const float* idata     = (const float*)d_in[0];
    const float* qdata     = (const float*)d_in[1];
    const float* angles    = (const float*)d_in[2];
    const float* ele_pos   = (const float*)d_in[3];
    const float* time_zero = (const float*)d_in[4];
    const float* grid      = (const float*)d_in[5];
    const float* w1 = (const float*)d_in[6],  *b1 = (const float*)d_in[7];
    const float* g1 = (const float*)d_in[8],  *be1 = (const float*)d_in[9];
    const float* w2 = (const float*)d_in[10], *b2 = (const float*)d_in[11];
    const float* g2 = (const float*)d_in[12], *be2 = (const float*)d_in[13];
    const float* w3 = (const float*)d_in[14], *b3 = (const float*)d_in[15];
    const float* g3 = (const float*)d_in[16], *be3 = (const float*)d_in[17];
    const float* w4 = (const float*)d_in[18], *b4 = (const float*)d_in[19];
    const float* g4 = (const float*)d_in[20], *be4 = (const float*)d_in[21];
    float* out = (float*)d_out;

    {
        dim3 bl(32, 32), gr(NE / 32, NS / 32);
        k_tr<<<gr, bl>>>(idata, qdata);   // transpose + global init
    }
    k_nrm<<<(NTOT / 16) / 256, 256>>>(idata, qdata);   // 1024 blocks
    k_bfconv1<<<NPIX / 4, 256>>>(angles, ele_pos, time_zero, grid, w1, b1);
    k_conv23<<<NPIX / 8, 256>>>(w2, b2, g1, be1, 1, 0);  // BN1; in A -> out B
    k_conv23<<<NPIX / 8, 256>>>(w3, b3, g2, be2, 2, 1);  // BN2; in B -> out A
    k_conv4 <<<NPIX / 8, 1024>>>(w4, b4, g3, be3);       // BN3; in A -> wraw
    k_final<<<NPIX / 4, 512>>>(g4, be4);
    k_sub<<<NPIX / 256, 256>>>(out);
}

// round 16
// speedup vs baseline: 1.0222x; 1.0222x over previous
#include <cuda_runtime.h>
#include <math.h>
#include <math_constants.h>

#define NPIX  32768      // 128*256 pixels
#define NE    128
#define NS    2048
#define NTOT  (16*128*2048)
#define CNT   4194304.0  // per-channel BN count = NPIX*NE

typedef unsigned long long u64;

// float2-index skew: stride-8 thread bases -> stride 9 (conflict-free wavefronts)
#define XA0(c) ((c) + ((c) >> 3))

// ---------------- scratch ----------------
__device__ float    g_iT[NS * NE];           // event-0 I, transposed [s][e]
__device__ float    g_qT[NS * NE];           // event-0 Q, transposed [s][e]
__device__ float    g_actA[NPIX * 8 * NE];
__device__ float    g_actB[NPIX * 8 * NE];
__device__ float    g_wraw[NPIX * NE];
__device__ float    g_sumI[NPIX];
__device__ float    g_sumQ[NPIX];
__device__ float    g_ydb [NPIX];
__device__ unsigned g_maxsq;
__device__ unsigned g_maxydb;
__device__ double   g_stats[4][16];   // per-layer [sum(8) | sumsq(8)]

__device__ __forceinline__ unsigned ford(float f) {
    unsigned u = __float_as_uint(f);
    return (u & 0x80000000u) ? ~u : (u | 0x80000000u);
}

// packed fp32x2 helpers (lanes = two pixels)
__device__ __forceinline__ u64 ffma2(u64 a, u64 b, u64 c) {
    u64 d;
    asm("fma.rn.f32x2 %0,%1,%2,%3;" : "=l"(d) : "l"(a), "l"(b), "l"(c));
    return d;
}
__device__ __forceinline__ u64 pack2(float lo, float hi) {
    u64 d;
    asm("mov.b64 %0,{%1,%2};" : "=l"(d) : "f"(lo), "f"(hi));
    return d;
}
__device__ __forceinline__ void unpack2(u64 a, float& lo, float& hi) {
    asm("mov.b64 {%0,%1},%2;" : "=f"(lo), "=f"(hi) : "l"(a));
}

// transpose event-0 I/Q: [e][s] -> [s][e]; also does global init (runs first in stream)
__global__ void k_tr(const float* __restrict__ id, const float* __restrict__ qd) {
    __shared__ float ti[32][33], tq[32][33];
    int e0 = blockIdx.x * 32, s0 = blockIdx.y * 32;
    int tx = threadIdx.x, ty = threadIdx.y;
    if (blockIdx.x == 0 && blockIdx.y == 0 && ty == 0) {
        int t = tx;
        if (t < 32) { ((double*)g_stats)[t] = 0.0; ((double*)g_stats)[t + 32] = 0.0; }
        if (t == 0) { g_maxsq = 0u; g_maxydb = 0u; }
    }
    ti[ty][tx] = id[(e0 + ty) * NS + s0 + tx];
    tq[ty][tx] = qd[(e0 + ty) * NS + s0 + tx];
    __syncthreads();
    g_iT[(s0 + ty) * NE + e0 + tx] = ti[tx][ty];
    g_qT[(s0 + ty) * NE + e0 + tx] = tq[tx][ty];
}

// max of i^2+q^2: one pass, 4 independent float4-pairs per thread (MLP=8)
// launched with exactly (NTOT/16)/256 = 1024 blocks of 256 threads
__global__ void __launch_bounds__(256) k_nrm(const float* __restrict__ id,
                                             const float* __restrict__ qd) {
    const float4* i4 = (const float4*)id;
    const float4* q4 = (const float4*)qd;
    const int S = (NTOT / 4) / 4;   // 262144
    int i = blockIdx.x * blockDim.x + threadIdx.x;   // 0..262143
    float4 a0 = i4[i], a1 = i4[i + S], a2 = i4[i + 2 * S], a3 = i4[i + 3 * S];
    float4 b0 = q4[i], b1 = q4[i + S], b2 = q4[i + 2 * S], b3 = q4[i + 3 * S];
    float m = 0.f;
    m = fmaxf(m, a0.x * a0.x + b0.x * b0.x); m = fmaxf(m, a0.y * a0.y + b0.y * b0.y);
    m = fmaxf(m, a0.z * a0.z + b0.z * b0.z); m = fmaxf(m, a0.w * a0.w + b0.w * b0.w);
    m = fmaxf(m, a1.x * a1.x + b1.x * b1.x); m = fmaxf(m, a1.y * a1.y + b1.y * b1.y);
    m = fmaxf(m, a1.z * a1.z + b1.z * b1.z); m = fmaxf(m, a1.w * a1.w + b1.w * b1.w);
    m = fmaxf(m, a2.x * a2.x + b2.x * b2.x); m = fmaxf(m, a2.y * a2.y + b2.y * b2.y);
    m = fmaxf(m, a2.z * a2.z + b2.z * b2.z); m = fmaxf(m, a2.w * a2.w + b2.w * b2.w);
    m = fmaxf(m, a3.x * a3.x + b3.x * b3.x); m = fmaxf(m, a3.y * a3.y + b3.y * b3.y);
    m = fmaxf(m, a3.z * a3.z + b3.z * b3.z); m = fmaxf(m, a3.w * a3.w + b3.w * b3.w);
    for (int off = 16; off; off >>= 1) m = fmaxf(m, __shfl_down_sync(0xffffffffu, m, off));
    __shared__ float sm[8];
    int lane = threadIdx.x & 31, w = threadIdx.x >> 5;
    if (lane == 0) sm[w] = m;
    __syncthreads();
    if (threadIdx.x == 0) {
        float mm = sm[0];
        for (int i2 = 1; i2 < 8; i2++) mm = fmaxf(mm, sm[i2]);
        atomicMax(&g_maxsq, __float_as_uint(mm));
    }
}

// ====== fused beamform + conv1 (2->8, K=65, pad=32); dual-pixel f32x2; 8 px/block ======
__global__ void __launch_bounds__(512, 2) k_bfconv1(
        const float* __restrict__ angles, const float* __restrict__ ele_pos,
        const float* __restrict__ time_zero, const float* __restrict__ grid,
        const float* __restrict__ w, const float* __restrict__ b) {
    __shared__ float2 swd[1040];        // weights duplicated (w,w), [co][ci][k]
    __shared__ float2 sxp[4][2][220];   // 4 pixel-pairs; XA0(191)=214
    __shared__ float  sred[16];
    __shared__ float2 sIw[4][4], sQw[4][4];
    int tid = threadIdx.x;
    int pbase = blockIdx.x * 8;

    for (int i = tid; i < 1040; i += 512) { float v = w[i]; swd[i] = make_float2(v, v); }
    if (tid < 16) sred[tid] = 0.f;
    // zero halo: 4pp x 2c x 64 = 512 entries (exactly one per thread)
    {
        int i = tid;
        int h  = i & 63;
        int c  = (i >> 6) & 1;
        int pp = i >> 7;                     // 0..3
        int x  = (h < 32) ? h : (128 + h);   // [0,32) or [160,192)
        sxp[pp][c][XA0(x)] = make_float2(0.f, 0.f);
    }
    __syncthreads();

    // ---- beamform phase: thread = (pair pp, element e) ----
    {
        int pp = tid >> 7, e = tid & 127;
        int p0 = pbase + 2 * pp, p1 = p0 + 1;
        float ang = angles[0];
        float sA, cA;
        sincosf(ang, &sA, &cA);
        float tanA = tanf(ang);
        float tz = time_zero[0];
        float ex  = ele_pos[e * 3];
        float ex0 = ele_pos[0];
        float exL = ele_pos[(NE - 1) * 3];

        float x0 = grid[p0 * 3 + 0], z0 = grid[p0 * 3 + 2];
        float x1 = grid[p1 * 3 + 0], z1 = grid[p1 * 3 + 2];

        const float FSC = (float)(20832000.0 / 1540.0);
        float txdel0 = (x0 * sA + z0 * cA + tz * 1540.0f) * FSC;
        float vx0 = x0 - ex;
        float dist0 = sqrtf(vx0 * vx0 + z0 * z0);
        float delays0 = txdel0 + dist0 * FSC;
        float d00 = floorf(delays0);
        float frac0 = delays0 - d00;
        int i00 = (int)d00;
        float txdel1 = (x1 * sA + z1 * cA + tz * 1540.0f) * FSC;
        float vx1 = x1 - ex;
        float dist1 = sqrtf(vx1 * vx1 + z1 * z1);
        float delays1 = txdel1 + dist1 * FSC;
        float d01 = floorf(delays1);
        float frac1 = delays1 - d01;
        int i01 = (int)d01;

        bool a0 = (i00 >= 0 && i00 < NS), a1 = (i00 + 1 >= 0 && i00 + 1 < NS);
        bool b0 = (i01 >= 0 && i01 < NS), b1 = (i01 + 1 >= 0 && i01 + 1 < NS);
        float iv00 = a0 ? g_iT[i00 * NE + e]       : 0.f;
        float iv01 = a1 ? g_iT[(i00 + 1) * NE + e] : 0.f;
        float qv00 = a0 ? g_qT[i00 * NE + e]       : 0.f;
        float qv01 = a1 ? g_qT[(i00 + 1) * NE + e] : 0.f;
        float iv10 = b0 ? g_iT[i01 * NE + e]       : 0.f;
        float iv11 = b1 ? g_iT[(i01 + 1) * NE + e] : 0.f;
        float qv10 = b0 ? g_qT[i01 * NE + e]       : 0.f;
        float qv11 = b1 ? g_qT[(i01 + 1) * NE + e] : 0.f;

        float invn = rsqrtf(__uint_as_float(g_maxsq));
        float ifoc0 = (iv00 * (1.f - frac0) + iv01 * frac0) * invn;
        float qfoc0 = (qv00 * (1.f - frac0) + qv01 * frac0) * invn;
        float ifoc1 = (iv10 * (1.f - frac1) + iv11 * frac1) * invn;
        float qfoc1 = (qv10 * (1.f - frac1) + qv11 * frac1) * invn;

        float tshift0 = delays0 / 20832000.0f - (z0 * 2.0f) / 1540.0f;
        float theta0 = (float)(2.0 * CUDART_PI * 5208000.0) * tshift0;
        float st0, ct0;
        sincosf(theta0, &st0, &ct0);
        float tshift1 = delays1 / 20832000.0f - (z1 * 2.0f) / 1540.0f;
        float theta1 = (float)(2.0 * CUDART_PI * 5208000.0) * tshift1;
        float st1, ct1;
        sincosf(theta1, &st1, &ct1);

        float ir0 = ifoc0 * ct0 - qfoc0 * st0;
        float qr0 = qfoc0 * ct0 + ifoc0 * st0;
        float ir1 = ifoc1 * ct1 - qfoc1 * st1;
        float qr1 = qfoc1 * ct1 + ifoc1 * st1;

        {
            float avx = fabsf(vx0);
            bool mrx = (fabsf(z0) > avx) || (avx <= 0.001f) ||
                       ((vx0 >= 0.001f)  && (x0 <= ex0)) ||
                       ((vx0 <= -0.001f) && (x0 >= exL));
            float xp = x0 - z0 * tanA;
            bool mtx = (xp >= ex0 * 1.2f) && (xp <= exL * 1.2f);
            if (!(mrx && mtx)) { ir0 = 0.f; qr0 = 0.f; }
        }
        {
            float avx = fabsf(vx1);
            bool mrx = (fabsf(z1) > avx) || (avx <= 0.001f) ||
                       ((vx1 >= 0.001f)  && (x1 <= ex0)) ||
                       ((vx1 <= -0.001f) && (x1 >= exL));
            float xp = x1 - z1 * tanA;
            bool mtx = (xp >= ex0 * 1.2f) && (xp <= exL * 1.2f);
            if (!(mrx && mtx)) { ir1 = 0.f; qr1 = 0.f; }
        }

        sxp[pp][0][XA0(e + 32)] = make_float2(ir0, ir1);
        sxp[pp][1][XA0(e + 32)] = make_float2(qr0, qr1);

        float a0s = ir0, a1s = ir1, b0s = qr0, b1s = qr1;
        for (int off = 16; off; off >>= 1) {
            a0s += __shfl_down_sync(0xffffffffu, a0s, off);
            a1s += __shfl_down_sync(0xffffffffu, a1s, off);
            b0s += __shfl_down_sync(0xffffffffu, b0s, off);
            b1s += __shfl_down_sync(0xffffffffu, b1s, off);
        }
        int lane = e & 31, wix = e >> 5;
        if (lane == 0) { sIw[pp][wix] = make_float2(a0s, a1s); sQw[pp][wix] = make_float2(b0s, b1s); }
    }
    __syncthreads();
    if (tid < 4) {
        int pp = tid;
        int p0 = pbase + 2 * pp;
        g_sumI[p0]     = sIw[pp][0].x + sIw[pp][1].x + sIw[pp][2].x + sIw[pp][3].x;
        g_sumI[p0 + 1] = sIw[pp][0].y + sIw[pp][1].y + sIw[pp][2].y + sIw[pp][3].y;
        g_sumQ[p0]     = sQw[pp][0].x + sQw[pp][1].x + sQw[pp][2].x + sQw[pp][3].x;
        g_sumQ[p0 + 1] = sQw[pp][0].y + sQw[pp][1].y + sQw[pp][2].y + sQw[pp][3].y;
    }

    // ---- conv1 phase ----
    int pp = tid >> 7, t = tid & 127, co = t >> 4, g = t & 15;  // e0 = 8g
    float bias = b[co];
    u64 acc[8];
#pragma unroll
    for (int j = 0; j < 8; j++) acc[j] = pack2(bias, bias);

#pragma unroll
    for (int ci = 0; ci < 2; ci++) {
        const u64* wp  = (const u64*)&swd[(co * 2 + ci) * 65];
        const u64* spg = ((const u64*)&sxp[pp][ci][0]) + 9 * g;  // XA(e0)=9g
        u64 pe[15];
#pragma unroll
        for (int i = 0; i < 15; i++) pe[i] = spg[XA0(i)];
#pragma unroll
        for (int kb = 0; kb < 64; kb += 8) {
#pragma unroll
            for (int k = 0; k < 8; k++) {
                u64 wk = wp[kb + k];
#pragma unroll
                for (int j = 0; j < 8; j++) acc[j] = ffma2(wk, pe[k + j], acc[j]);
            }
#pragma unroll
            for (int i = 0; i < 7; i++) pe[i] = pe[i + 8];
            if (kb < 56) {
#pragma unroll
                for (int i = 7; i < 15; i++) pe[i] = spg[XA0(kb + 8 + i)];
            } else {
                pe[7] = spg[XA0(71)];
            }
        }
        u64 wl = wp[64];
#pragma unroll
        for (int j = 0; j < 8; j++) acc[j] = ffma2(wl, pe[j], acc[j]);
    }

    int p0 = pbase + pp * 2;
    float f0[8], f1[8];
    float s = 0.f, ss = 0.f;
#pragma unroll
    for (int j = 0; j < 8; j++) {
        unpack2(acc[j], f0[j], f1[j]);
        s += f0[j] + f1[j];
        ss += f0[j] * f0[j] + f1[j] * f1[j];
    }
    float4* o0 = (float4*)&g_actA[p0 * 1024 + co * 128 + g * 8];
    float4* o1 = (float4*)&g_actA[(p0 + 1) * 1024 + co * 128 + g * 8];
    o0[0] = make_float4(f0[0], f0[1], f0[2], f0[3]);
    o0[1] = make_float4(f0[4], f0[5], f0[6], f0[7]);
    o1[0] = make_float4(f1[0], f1[1], f1[2], f1[3]);
    o1[1] = make_float4(f1[4], f1[5], f1[6], f1[7]);
    for (int off = 8; off; off >>= 1) {
        s  += __shfl_down_sync(0xffffffffu, s,  off, 16);
        ss += __shfl_down_sync(0xffffffffu, ss, off, 16);
    }
    if (g == 0) { atomicAdd(&sred[co], s); atomicAdd(&sred[8 + co], ss); }
    __syncthreads();
    if (tid < 8) {
        atomicAdd(&g_stats[0][tid],     (double)sred[tid]);
        atomicAdd(&g_stats[0][8 + tid], (double)sred[8 + tid]);
    }
}

// ====== conv2/3: BN(prev)+relu on load; 8->8, K=15; dual-pixel f32x2; 2 co/thread ======
__global__ void __launch_bounds__(256, 3) k_conv23(const float* __restrict__ w,
                                                   const float* __restrict__ b,
                                                   const float* __restrict__ gam,
                                                   const float* __restrict__ bet,
                                                   int layer, int flip) {
    __shared__ float2 swd[960];         // duplicated weights [co][ci][k]
    __shared__ float2 sxp[4][8][164];   // 4 pixel-pairs; XA0(141)=158
    __shared__ float  ssc[8], ssh[8];
    __shared__ float  sred[16];
    const float* in  = flip ? g_actB : g_actA;
    float*       out = flip ? g_actA : g_actB;

    int tid = threadIdx.x;
    int pbase = blockIdx.x * 8;         // 8 pixels per block

    for (int i = tid; i < 960; i += 256) { float v = w[i]; swd[i] = make_float2(v, v); }
    if (tid < 8) {
        double mu  = g_stats[layer - 1][tid] / CNT;
        double var = g_stats[layer - 1][8 + tid] / CNT - mu * mu;
        float sc = (float)((double)gam[tid] / sqrt(var + 1e-5));
        ssc[tid] = sc;
        ssh[tid] = bet[tid] - (float)mu * sc;
    }
    if (tid < 16) sred[tid] = 0.f;
    for (int i = tid; i < 448; i += 256) {
        int h  = i % 14;
        int c  = (i / 14) & 7;
        int pp = i / 112;
        int x  = (h < 7) ? h : (128 + h);
        sxp[pp][c][XA0(x)] = make_float2(0.f, 0.f);
    }
    __syncthreads();

#pragma unroll
    for (int it = 0; it < 4; it++) {
        int i  = tid + it * 256;
        int e4 = i & 31;
        int c  = (i >> 5) & 7;
        int pp = i >> 8;
        int p0 = pbase + pp * 2;
        float sc = ssc[c], sh = ssh[c];
        float4 a = *(const float4*)&in[p0 * 1024 + c * 128 + e4 * 4];
        float4 d = *(const float4*)&in[(p0 + 1) * 1024 + c * 128 + e4 * 4];
        int xb = e4 * 4 + 7;
        sxp[pp][c][XA0(xb + 0)] = make_float2(fmaxf(fmaf(a.x, sc, sh), 0.f), fmaxf(fmaf(d.x, sc, sh), 0.f));
        sxp[pp][c][XA0(xb + 1)] = make_float2(fmaxf(fmaf(a.y, sc, sh), 0.f), fmaxf(fmaf(d.y, sc, sh), 0.f));
        sxp[pp][c][XA0(xb + 2)] = make_float2(fmaxf(fmaf(a.z, sc, sh), 0.f), fmaxf(fmaf(d.z, sc, sh), 0.f));
        sxp[pp][c][XA0(xb + 3)] = make_float2(fmaxf(fmaf(a.w, sc, sh), 0.f), fmaxf(fmaf(d.w, sc, sh), 0.f));
    }
    __syncthreads();

    int pp = tid >> 6, cop = (tid >> 4) & 3, g = tid & 15;
    int co0 = 2 * cop, co1 = 2 * cop + 1;
    u64 acc0[8], acc1[8];
    {
        float b0v = b[co0], b1v = b[co1];
#pragma unroll
        for (int j = 0; j < 8; j++) { acc0[j] = pack2(b0v, b0v); acc1[j] = pack2(b1v, b1v); }
    }

#pragma unroll
    for (int ci = 0; ci < 8; ci++) {
        const u64* wp0 = (const u64*)&swd[(co0 * 8 + ci) * 15];
        const u64* wp1 = (const u64*)&swd[(co1 * 8 + ci) * 15];
        const u64* spg = ((const u64*)&sxp[pp][ci][0]) + 9 * g;
        u64 pe[15];
#pragma unroll
        for (int i = 0; i < 15; i++) pe[i] = spg[XA0(i)];
#pragma unroll
        for (int k = 0; k < 8; k++) {
            u64 w0 = wp0[k], w1 = wp1[k];
#pragma unroll
            for (int j = 0; j < 8; j++) acc0[j] = ffma2(w0, pe[k + j], acc0[j]);
#pragma unroll
            for (int j = 0; j < 8; j++) acc1[j] = ffma2(w1, pe[k + j], acc1[j]);
        }
#pragma unroll
        for (int i = 0; i < 7; i++) pe[i] = pe[i + 8];
#pragma unroll
        for (int i = 7; i < 14; i++) pe[i] = spg[XA0(i + 8)];
#pragma unroll
        for (int k = 8; k < 15; k++) {
            u64 w0 = wp0[k], w1 = wp1[k];
#pragma unroll
            for (int j = 0; j < 8; j++) acc0[j] = ffma2(w0, pe[k - 8 + j], acc0[j]);
#pragma unroll
            for (int j = 0; j < 8; j++) acc1[j] = ffma2(w1, pe[k - 8 + j], acc1[j]);
        }
    }

    int p0 = pbase + pp * 2;
    float f0[8], f1[8], h0[8], h1[8];
    float s0 = 0.f, ss0 = 0.f, s1 = 0.f, ss1 = 0.f;
#pragma unroll
    for (int j = 0; j < 8; j++) {
        unpack2(acc0[j], f0[j], f1[j]);
        unpack2(acc1[j], h0[j], h1[j]);
        s0 += f0[j] + f1[j];  ss0 += f0[j] * f0[j] + f1[j] * f1[j];
        s1 += h0[j] + h1[j];  ss1 += h0[j] * h0[j] + h1[j] * h1[j];
    }
    {
        float4* o = (float4*)&out[p0 * 1024 + co0 * 128 + g * 8];
        o[0] = make_float4(f0[0], f0[1], f0[2], f0[3]);
        o[1] = make_float4(f0[4], f0[5], f0[6], f0[7]);
        o = (float4*)&out[(p0 + 1) * 1024 + co0 * 128 + g * 8];
        o[0] = make_float4(f1[0], f1[1], f1[2], f1[3]);
        o[1] = make_float4(f1[4], f1[5], f1[6], f1[7]);
        o = (float4*)&out[p0 * 1024 + co1 * 128 + g * 8];
        o[0] = make_float4(h0[0], h0[1], h0[2], h0[3]);
        o[1] = make_float4(h0[4], h0[5], h0[6], h0[7]);
        o = (float4*)&out[(p0 + 1) * 1024 + co1 * 128 + g * 8];
        o[0] = make_float4(h1[0], h1[1], h1[2], h1[3]);
        o[1] = make_float4(h1[4], h1[5], h1[6], h1[7]);
    }
    for (int off = 8; off; off >>= 1) {
        s0  += __shfl_down_sync(0xffffffffu, s0,  off, 16);
        ss0 += __shfl_down_sync(0xffffffffu, ss0, off, 16);
        s1  += __shfl_down_sync(0xffffffffu, s1,  off, 16);
        ss1 += __shfl_down_sync(0xffffffffu, ss1, off, 16);
    }
    if (g == 0) {
        atomicAdd(&sred[co0], s0); atomicAdd(&sred[8 + co0], ss0);
        atomicAdd(&sred[co1], s1); atomicAdd(&sred[8 + co1], ss1);
    }
    __syncthreads();
    if (tid < 8) {
        atomicAdd(&g_stats[layer][tid],     (double)sred[tid]);
        atomicAdd(&g_stats[layer][8 + tid], (double)sred[8 + tid]);
    }
}

// ---- conv4: BN3+relu fused; 8->1, K=3, pad=1; float4 loads (R13 version) ----
__global__ void __launch_bounds__(512) k_conv4(const float* __restrict__ w,
                                               const float* __restrict__ b,
                                               const float* __restrict__ gam,
                                               const float* __restrict__ bet) {
    __shared__ float sw[24];
    __shared__ float ssc[8], ssh[8];
    __shared__ float sx[4][8][130];
    __shared__ float sred[32];
    int tid = threadIdx.x;
    int pbase = blockIdx.x * 4;

    if (tid < 24) sw[tid] = w[tid];
    if (tid < 8) {
        double mu  = g_stats[2][tid] / CNT;
        double var = g_stats[2][8 + tid] / CNT - mu * mu;
        float sc = (float)((double)gam[tid] / sqrt(var + 1e-5));
        ssc[tid] = sc;
        ssh[tid] = bet[tid] - (float)mu * sc;
    }
    if (tid >= 448) {
        int i  = tid - 448;
        int lp = i >> 4;
        int c  = (i >> 1) & 7;
        int xi = (i & 1) ? 129 : 0;
        sx[lp][c][xi] = 0.f;
    }
    __syncthreads();

#pragma unroll
    for (int it = 0; it < 2; it++) {
        int i  = tid + it * 512;
        int e4 = i & 31;
        int c  = (i >> 5) & 7;
        int lp = i >> 8;
        float sc = ssc[c], sh = ssh[c];
        float4 a = *(const float4*)&g_actA[(pbase + lp) * 1024 + c * 128 + e4 * 4];
        int xb = e4 * 4 + 1;
        sx[lp][c][xb + 0] = fmaxf(fmaf(a.x, sc, sh), 0.f);
        sx[lp][c][xb + 1] = fmaxf(fmaf(a.y, sc, sh), 0.f);
        sx[lp][c][xb + 2] = fmaxf(fmaf(a.z, sc, sh), 0.f);
        sx[lp][c][xb + 3] = fmaxf(fmaf(a.w, sc, sh), 0.f);
    }
    __syncthreads();

    int lp = tid >> 7, e = tid & 127;
    float acc = b[0];
#pragma unroll
    for (int ci = 0; ci < 8; ci++)
#pragma unroll
        for (int k = 0; k < 3; k++)
            acc = fmaf(sw[ci * 3 + k], sx[lp][ci][e + k], acc);

    g_wraw[(pbase + lp) * 128 + e] = acc;

    float s = acc, ss = acc * acc;
    for (int off = 16; off; off >>= 1) {
        s  += __shfl_down_sync(0xffffffffu, s,  off);
        ss += __shfl_down_sync(0xffffffffu, ss, off);
    }
    int lane = tid & 31, wix = tid >> 5;
    if (lane == 0) { sred[wix] = s; sred[16 + wix] = ss; }
    __syncthreads();
    if (tid == 0) {
        float S = 0.f, SS = 0.f;
        for (int i = 0; i < 16; i++) { S += sred[i]; SS += sred[16 + i]; }
        atomicAdd(&g_stats[3][0], (double)S);
        atomicAdd(&g_stats[3][1], (double)SS);
    }
}

// ---- BN4+relu+weight-sum+compound+dB; 4 pixels per 512-thread block (R13 version) ----
__global__ void __launch_bounds__(512) k_final(const float* __restrict__ gam,
                                               const float* __restrict__ bet) {
    int tid = threadIdx.x;
    int lp = tid >> 7, e = tid & 127;
    int p = blockIdx.x * 4 + lp;
    double mu  = g_stats[3][0] / CNT;
    double var = g_stats[3][1] / CNT - mu * mu;
    float sc = (float)((double)gam[0] / sqrt(var + 1e-5));
    float sh = bet[0] - (float)mu * sc;
    float wv = fmaxf(fmaf(g_wraw[p * 128 + e], sc, sh), 0.f);
    for (int off = 16; off; off >>= 1) wv += __shfl_down_sync(0xffffffffu, wv, off);
    __shared__ float sm[4][4];
    int lane = e & 31, w = e >> 5;
    if (lane == 0) sm[lp][w] = wv;
    __syncthreads();
    if (e == 0) {
        float sW = sm[lp][0] + sm[lp][1] + sm[lp][2] + sm[lp][3];
        float cI = sW * g_sumI[p] * (1.0f / 128.0f);
        float cQ = sW * g_sumQ[p] * (1.0f / 128.0f);
        float mag = sqrtf(cI * cI + cQ * cQ);
        g_ydb[p] = 20.0f * log10f(mag + 1e-20f);
    }
}

__global__ void k_max() {
    float m = -CUDART_INF_F;
    for (int i = blockIdx.x * blockDim.x + threadIdx.x; i < NPIX; i += gridDim.x * blockDim.x)
        m = fmaxf(m, g_ydb[i]);
    for (int off = 16; off; off >>= 1) m = fmaxf(m, __shfl_down_sync(0xffffffffu, m, off));
    __shared__ float sm[8];
    int lane = threadIdx.x & 31, w = threadIdx.x >> 5;
    if (lane == 0) sm[w] = m;
    __syncthreads();
    if (threadIdx.x == 0) {
        float mm = sm[0];
        for (int i = 1; i < (int)(blockDim.x >> 5); i++) mm = fmaxf(mm, sm[i]);
        atomicMax(&g_maxydb, ford(mm));
    }
}

__global__ void k_sub(float* __restrict__ out) {
    int i = blockIdx.x * blockDim.x + threadIdx.x;
    unsigned u = g_maxydb;
    float mx = (u & 0x80000000u) ? __uint_as_float(u & 0x7fffffffu) : __uint_as_float(~u);
    if (i < NPIX) out[i] = g_ydb[i] - mx;
}

extern "C" void kernel_launch(void* const* d_in, const int* in_sizes, int n_in,
                              void* d_out, int out_size) {
    const float* idata     = (const float*)d_in[0];
    const float* qdata     = (const float*)d_in[1];
    const float* angles    = (const float*)d_in[2];
    const float* ele_pos   = (const float*)d_in[3];
    const float* time_zero = (const float*)d_in[4];
    const float* grid      = (const float*)d_in[5];
    const float* w1 = (const float*)d_in[6],  *b1 = (const float*)d_in[7];
    const float* g1 = (const float*)d_in[8],  *be1 = (const float*)d_in[9];
    const float* w2 = (const float*)d_in[10], *b2 = (const float*)d_in[11];
    const float* g2 = (const float*)d_in[12], *be2 = (const float*)d_in[13];
    const float* w3 = (const float*)d_in[14], *b3 = (const float*)d_in[15];
    const float* g3 = (const float*)d_in[16], *be3 = (const float*)d_in[17];
    const float* w4 = (const float*)d_in[18], *b4 = (const float*)d_in[19];
    const float* g4 = (const float*)d_in[20], *be4 = (const float*)d_in[21];
    float* out = (float*)d_out;

    {
        dim3 bl(32, 32), gr(NE / 32, NS / 32);
        k_tr<<<gr, bl>>>(idata, qdata);   // transpose + global init
    }
    k_nrm<<<(NTOT / 16) / 256, 256>>>(idata, qdata);   // 1024 blocks, exact cover
    k_bfconv1<<<NPIX / 8, 512>>>(angles, ele_pos, time_zero, grid, w1, b1);
    k_conv23<<<NPIX / 8, 256>>>(w2, b2, g1, be1, 1, 0);  // BN1; in A -> out B
    k_conv23<<<NPIX / 8, 256>>>(w3, b3, g2, be2, 2, 1);  // BN2; in B -> out A
    k_conv4 <<<NPIX / 4, 512>>>(w4, b4, g3, be3);        // BN3; in A -> wraw
    k_final<<<NPIX / 4, 512>>>(g4, be4);
    k_max<<<64, 256>>>();
    k_sub<<<NPIX / 256, 256>>>(out);
}

// round 17
// speedup vs baseline: 1.0384x; 1.0158x over previous
#include <cuda_runtime.h>
#include <math.h>
#include <math_constants.h>

#define NPIX  32768      // 128*256 pixels
#define NE    128
#define NS    2048
#define NTOT  (16*128*2048)
#define CNT   4194304.0  // per-channel BN count = NPIX*NE

typedef unsigned long long u64;

// float2-index skew: stride-8 thread bases -> stride 9 (conflict-free wavefronts)
#define XA0(c) ((c) + ((c) >> 3))

// ---------------- scratch ----------------
__device__ float    g_iT[NS * NE];           // event-0 I, transposed [s][e]
__device__ float    g_qT[NS * NE];           // event-0 Q, transposed [s][e]
__device__ float    g_actA[NPIX * 8 * NE];
__device__ float    g_actB[NPIX * 8 * NE];
__device__ float    g_wraw[NPIX * NE];
__device__ float    g_sumI[NPIX];
__device__ float    g_sumQ[NPIX];
__device__ float    g_ydb [NPIX];
__device__ unsigned g_maxsq;
__device__ unsigned g_maxydb;
__device__ double   g_stats[4][16];   // per-layer [sum(8) | sumsq(8)]

__device__ __forceinline__ unsigned ford(float f) {
    unsigned u = __float_as_uint(f);
    return (u & 0x80000000u) ? ~u : (u | 0x80000000u);
}

// packed fp32x2 helpers (lanes = two pixels)
__device__ __forceinline__ u64 ffma2(u64 a, u64 b, u64 c) {
    u64 d;
    asm("fma.rn.f32x2 %0,%1,%2,%3;" : "=l"(d) : "l"(a), "l"(b), "l"(c));
    return d;
}
__device__ __forceinline__ u64 pack2(float lo, float hi) {
    u64 d;
    asm("mov.b64 %0,{%1,%2};" : "=l"(d) : "f"(lo), "f"(hi));
    return d;
}
__device__ __forceinline__ void unpack2(u64 a, float& lo, float& hi) {
    asm("mov.b64 {%0,%1},%2;" : "=f"(lo), "=f"(hi) : "l"(a));
}

// transpose event-0 I/Q: [e][s] -> [s][e]; also does global init (runs first in stream)
__global__ void k_tr(const float* __restrict__ id, const float* __restrict__ qd) {
    __shared__ float ti[32][33], tq[32][33];
    int e0 = blockIdx.x * 32, s0 = blockIdx.y * 32;
    int tx = threadIdx.x, ty = threadIdx.y;
    if (blockIdx.x == 0 && blockIdx.y == 0 && ty == 0) {
        int t = tx;
        if (t < 32) { ((double*)g_stats)[t] = 0.0; ((double*)g_stats)[t + 32] = 0.0; }
        if (t == 0) { g_maxsq = 0u; g_maxydb = 0u; }
    }
    ti[ty][tx] = id[(e0 + ty) * NS + s0 + tx];
    tq[ty][tx] = qd[(e0 + ty) * NS + s0 + tx];
    __syncthreads();
    g_iT[(s0 + ty) * NE + e0 + tx] = ti[tx][ty];
    g_qT[(s0 + ty) * NE + e0 + tx] = tq[tx][ty];
}

// max of i^2+q^2: one pass, 4 independent float4-pairs per thread (MLP=8)
// launched with exactly (NTOT/16)/256 = 1024 blocks of 256 threads
__global__ void __launch_bounds__(256) k_nrm(const float* __restrict__ id,
                                             const float* __restrict__ qd) {
    const float4* i4 = (const float4*)id;
    const float4* q4 = (const float4*)qd;
    const int S = (NTOT / 4) / 4;   // 262144
    int i = blockIdx.x * blockDim.x + threadIdx.x;   // 0..262143
    float4 a0 = i4[i], a1 = i4[i + S], a2 = i4[i + 2 * S], a3 = i4[i + 3 * S];
    float4 b0 = q4[i], b1 = q4[i + S], b2 = q4[i + 2 * S], b3 = q4[i + 3 * S];
    float m = 0.f;
    m = fmaxf(m, a0.x * a0.x + b0.x * b0.x); m = fmaxf(m, a0.y * a0.y + b0.y * b0.y);
    m = fmaxf(m, a0.z * a0.z + b0.z * b0.z); m = fmaxf(m, a0.w * a0.w + b0.w * b0.w);
    m = fmaxf(m, a1.x * a1.x + b1.x * b1.x); m = fmaxf(m, a1.y * a1.y + b1.y * b1.y);
    m = fmaxf(m, a1.z * a1.z + b1.z * b1.z); m = fmaxf(m, a1.w * a1.w + b1.w * b1.w);
    m = fmaxf(m, a2.x * a2.x + b2.x * b2.x); m = fmaxf(m, a2.y * a2.y + b2.y * b2.y);
    m = fmaxf(m, a2.z * a2.z + b2.z * b2.z); m = fmaxf(m, a2.w * a2.w + b2.w * b2.w);
    m = fmaxf(m, a3.x * a3.x + b3.x * b3.x); m = fmaxf(m, a3.y * a3.y + b3.y * b3.y);
    m = fmaxf(m, a3.z * a3.z + b3.z * b3.z); m = fmaxf(m, a3.w * a3.w + b3.w * b3.w);
    for (int off = 16; off; off >>= 1) m = fmaxf(m, __shfl_down_sync(0xffffffffu, m, off));
    __shared__ float sm[8];
    int lane = threadIdx.x & 31, w = threadIdx.x >> 5;
    if (lane == 0) sm[w] = m;
    __syncthreads();
    if (threadIdx.x == 0) {
        float mm = sm[0];
        for (int i2 = 1; i2 < 8; i2++) mm = fmaxf(mm, sm[i2]);
        atomicMax(&g_maxsq, __float_as_uint(mm));
    }
}

// ============ fused beamform + conv1 (2->8, K=65, pad=32); dual-pixel f32x2 ============
__global__ void __launch_bounds__(256, 4) k_bfconv1(
        const float* __restrict__ angles, const float* __restrict__ ele_pos,
        const float* __restrict__ time_zero, const float* __restrict__ grid,
        const float* __restrict__ w, const float* __restrict__ b) {
    __shared__ float2 swd[1040];        // weights duplicated (w,w), [co][ci][k]
    __shared__ float2 sxp[2][2][220];   // (p0,p1) pairs, skewed; XA0(191)=214
    __shared__ float  sred[16];
    __shared__ float2 sIw[2][4], sQw[2][4];
    int tid = threadIdx.x;
    int pbase = blockIdx.x * 4;

    for (int i = tid; i < 1040; i += 256) { float v = w[i]; swd[i] = make_float2(v, v); }
    if (tid < 16) sred[tid] = 0.f;
    {
        int i = tid;
        int h  = i & 63;
        int c  = (i >> 6) & 1;
        int pp = i >> 7;
        int x  = (h < 32) ? h : (128 + h);
        sxp[pp][c][XA0(x)] = make_float2(0.f, 0.f);
    }
    __syncthreads();

    {
        int pp = tid >> 7, e = tid & 127;
        int p0 = pbase + 2 * pp, p1 = p0 + 1;
        float ang = angles[0];
        float sA, cA;
        sincosf(ang, &sA, &cA);
        float tanA = tanf(ang);
        float tz = time_zero[0];
        float ex  = ele_pos[e * 3];
        float ex0 = ele_pos[0];
        float exL = ele_pos[(NE - 1) * 3];

        float x0 = grid[p0 * 3 + 0], z0 = grid[p0 * 3 + 2];
        float x1 = grid[p1 * 3 + 0], z1 = grid[p1 * 3 + 2];

        const float FSC = (float)(20832000.0 / 1540.0);
        float txdel0 = (x0 * sA + z0 * cA + tz * 1540.0f) * FSC;
        float vx0 = x0 - ex;
        float dist0 = sqrtf(vx0 * vx0 + z0 * z0);
        float delays0 = txdel0 + dist0 * FSC;
        float d00 = floorf(delays0);
        float frac0 = delays0 - d00;
        int i00 = (int)d00;
        float txdel1 = (x1 * sA + z1 * cA + tz * 1540.0f) * FSC;
        float vx1 = x1 - ex;
        float dist1 = sqrtf(vx1 * vx1 + z1 * z1);
        float delays1 = txdel1 + dist1 * FSC;
        float d01 = floorf(delays1);
        float frac1 = delays1 - d01;
        int i01 = (int)d01;

        bool a0 = (i00 >= 0 && i00 < NS), a1 = (i00 + 1 >= 0 && i00 + 1 < NS);
        bool b0 = (i01 >= 0 && i01 < NS), b1 = (i01 + 1 >= 0 && i01 + 1 < NS);
        float iv00 = a0 ? g_iT[i00 * NE + e]       : 0.f;
        float iv01 = a1 ? g_iT[(i00 + 1) * NE + e] : 0.f;
        float qv00 = a0 ? g_qT[i00 * NE + e]       : 0.f;
        float qv01 = a1 ? g_qT[(i00 + 1) * NE + e] : 0.f;
        float iv10 = b0 ? g_iT[i01 * NE + e]       : 0.f;
        float iv11 = b1 ? g_iT[(i01 + 1) * NE + e] : 0.f;
        float qv10 = b0 ? g_qT[i01 * NE + e]       : 0.f;
        float qv11 = b1 ? g_qT[(i01 + 1) * NE + e] : 0.f;

        float invn = rsqrtf(__uint_as_float(g_maxsq));
        float ifoc0 = (iv00 * (1.f - frac0) + iv01 * frac0) * invn;
        float qfoc0 = (qv00 * (1.f - frac0) + qv01 * frac0) * invn;
        float ifoc1 = (iv10 * (1.f - frac1) + iv11 * frac1) * invn;
        float qfoc1 = (qv10 * (1.f - frac1) + qv11 * frac1) * invn;

        float tshift0 = delays0 / 20832000.0f - (z0 * 2.0f) / 1540.0f;
        float theta0 = (float)(2.0 * CUDART_PI * 5208000.0) * tshift0;
        float st0, ct0;
        sincosf(theta0, &st0, &ct0);
        float tshift1 = delays1 / 20832000.0f - (z1 * 2.0f) / 1540.0f;
        float theta1 = (float)(2.0 * CUDART_PI * 5208000.0) * tshift1;
        float st1, ct1;
        sincosf(theta1, &st1, &ct1);

        float ir0 = ifoc0 * ct0 - qfoc0 * st0;
        float qr0 = qfoc0 * ct0 + ifoc0 * st0;
        float ir1 = ifoc1 * ct1 - qfoc1 * st1;
        float qr1 = qfoc1 * ct1 + ifoc1 * st1;

        {
            float avx = fabsf(vx0);
            bool mrx = (fabsf(z0) > avx) || (avx <= 0.001f) ||
                       ((vx0 >= 0.001f)  && (x0 <= ex0)) ||
                       ((vx0 <= -0.001f) && (x0 >= exL));
            float xp = x0 - z0 * tanA;
            bool mtx = (xp >= ex0 * 1.2f) && (xp <= exL * 1.2f);
            if (!(mrx && mtx)) { ir0 = 0.f; qr0 = 0.f; }
        }
        {
            float avx = fabsf(vx1);
            bool mrx = (fabsf(z1) > avx) || (avx <= 0.001f) ||
                       ((vx1 >= 0.001f)  && (x1 <= ex0)) ||
                       ((vx1 <= -0.001f) && (x1 >= exL));
            float xp = x1 - z1 * tanA;
            bool mtx = (xp >= ex0 * 1.2f) && (xp <= exL * 1.2f);
            if (!(mrx && mtx)) { ir1 = 0.f; qr1 = 0.f; }
        }

        sxp[pp][0][XA0(e + 32)] = make_float2(ir0, ir1);
        sxp[pp][1][XA0(e + 32)] = make_float2(qr0, qr1);

        float a0s = ir0, a1s = ir1, b0s = qr0, b1s = qr1;
        for (int off = 16; off; off >>= 1) {
            a0s += __shfl_down_sync(0xffffffffu, a0s, off);
            a1s += __shfl_down_sync(0xffffffffu, a1s, off);
            b0s += __shfl_down_sync(0xffffffffu, b0s, off);
            b1s += __shfl_down_sync(0xffffffffu, b1s, off);
        }
        int lane = e & 31, wix = e >> 5;
        if (lane == 0) { sIw[pp][wix] = make_float2(a0s, a1s); sQw[pp][wix] = make_float2(b0s, b1s); }
    }
    __syncthreads();
    if (tid < 2) {
        int pp = tid;
        int p0 = pbase + 2 * pp;
        g_sumI[p0]     = sIw[pp][0].x + sIw[pp][1].x + sIw[pp][2].x + sIw[pp][3].x;
        g_sumI[p0 + 1] = sIw[pp][0].y + sIw[pp][1].y + sIw[pp][2].y + sIw[pp][3].y;
        g_sumQ[p0]     = sQw[pp][0].x + sQw[pp][1].x + sQw[pp][2].x + sQw[pp][3].x;
        g_sumQ[p0 + 1] = sQw[pp][0].y + sQw[pp][1].y + sQw[pp][2].y + sQw[pp][3].y;
    }

    int pp = tid >> 7, t = tid & 127, co = t >> 4, g = t & 15;  // e0 = 8g
    float bias = b[co];
    u64 acc[8];
#pragma unroll
    for (int j = 0; j < 8; j++) acc[j] = pack2(bias, bias);

#pragma unroll
    for (int ci = 0; ci < 2; ci++) {
        const u64* wp  = (const u64*)&swd[(co * 2 + ci) * 65];
        const u64* spg = ((const u64*)&sxp[pp][ci][0]) + 9 * g;  // XA(e0)=9g
        u64 pe[15];
#pragma unroll
        for (int i = 0; i < 15; i++) pe[i] = spg[XA0(i)];
#pragma unroll
        for (int kb = 0; kb < 64; kb += 8) {
#pragma unroll
            for (int k = 0; k < 8; k++) {
                u64 wk = wp[kb + k];
#pragma unroll
                for (int j = 0; j < 8; j++) acc[j] = ffma2(wk, pe[k + j], acc[j]);
            }
#pragma unroll
            for (int i = 0; i < 7; i++) pe[i] = pe[i + 8];
            if (kb < 56) {
#pragma unroll
                for (int i = 7; i < 15; i++) pe[i] = spg[XA0(kb + 8 + i)];
            } else {
                pe[7] = spg[XA0(71)];
            }
        }
        u64 wl = wp[64];
#pragma unroll
        for (int j = 0; j < 8; j++) acc[j] = ffma2(wl, pe[j], acc[j]);
    }

    int p0 = pbase + pp * 2;
    float f0[8], f1[8];
    float s = 0.f, ss = 0.f;
#pragma unroll
    for (int j = 0; j < 8; j++) {
        unpack2(acc[j], f0[j], f1[j]);
        s += f0[j] + f1[j];
        ss += f0[j] * f0[j] + f1[j] * f1[j];
    }
    float4* o0 = (float4*)&g_actA[p0 * 1024 + co * 128 + g * 8];
    float4* o1 = (float4*)&g_actA[(p0 + 1) * 1024 + co * 128 + g * 8];
    o0[0] = make_float4(f0[0], f0[1], f0[2], f0[3]);
    o0[1] = make_float4(f0[4], f0[5], f0[6], f0[7]);
    o1[0] = make_float4(f1[0], f1[1], f1[2], f1[3]);
    o1[1] = make_float4(f1[4], f1[5], f1[6], f1[7]);
    for (int off = 8; off; off >>= 1) {
        s  += __shfl_down_sync(0xffffffffu, s,  off, 16);
        ss += __shfl_down_sync(0xffffffffu, ss, off, 16);
    }
    if (g == 0) { atomicAdd(&sred[co], s); atomicAdd(&sred[8 + co], ss); }
    __syncthreads();
    if (tid < 8) {
        atomicAdd(&g_stats[0][tid],     (double)sred[tid]);
        atomicAdd(&g_stats[0][8 + tid], (double)sred[8 + tid]);
    }
}

// ====== conv2/3: BN(prev)+relu on load; 8->8, K=15; dual-pixel f32x2; 2 co/thread ======
__global__ void __launch_bounds__(256, 3) k_conv23(const float* __restrict__ w,
                                                   const float* __restrict__ b,
                                                   const float* __restrict__ gam,
                                                   const float* __restrict__ bet,
                                                   int layer, int flip) {
    __shared__ float2 swd[960];         // duplicated weights [co][ci][k]
    __shared__ float2 sxp[4][8][164];   // 4 pixel-pairs; XA0(141)=158
    __shared__ float  ssc[8], ssh[8];
    __shared__ float  sred[16];
    const float* in  = flip ? g_actB : g_actA;
    float*       out = flip ? g_actA : g_actB;

    int tid = threadIdx.x;
    int pbase = blockIdx.x * 8;         // 8 pixels per block

    for (int i = tid; i < 960; i += 256) { float v = w[i]; swd[i] = make_float2(v, v); }
    if (tid < 8) {
        double mu  = g_stats[layer - 1][tid] / CNT;
        double var = g_stats[layer - 1][8 + tid] / CNT - mu * mu;
        float sc = (float)((double)gam[tid] / sqrt(var + 1e-5));
        ssc[tid] = sc;
        ssh[tid] = bet[tid] - (float)mu * sc;
    }
    if (tid < 16) sred[tid] = 0.f;
    for (int i = tid; i < 448; i += 256) {
        int h  = i % 14;
        int c  = (i / 14) & 7;
        int pp = i / 112;
        int x  = (h < 7) ? h : (128 + h);
        sxp[pp][c][XA0(x)] = make_float2(0.f, 0.f);
    }
    __syncthreads();

#pragma unroll
    for (int it = 0; it < 4; it++) {
        int i  = tid + it * 256;
        int e4 = i & 31;
        int c  = (i >> 5) & 7;
        int pp = i >> 8;
        int p0 = pbase + pp * 2;
        float sc = ssc[c], sh = ssh[c];
        float4 a = *(const float4*)&in[p0 * 1024 + c * 128 + e4 * 4];
        float4 d = *(const float4*)&in[(p0 + 1) * 1024 + c * 128 + e4 * 4];
        int xb = e4 * 4 + 7;
        sxp[pp][c][XA0(xb + 0)] = make_float2(fmaxf(fmaf(a.x, sc, sh), 0.f), fmaxf(fmaf(d.x, sc, sh), 0.f));
        sxp[pp][c][XA0(xb + 1)] = make_float2(fmaxf(fmaf(a.y, sc, sh), 0.f), fmaxf(fmaf(d.y, sc, sh), 0.f));
        sxp[pp][c][XA0(xb + 2)] = make_float2(fmaxf(fmaf(a.z, sc, sh), 0.f), fmaxf(fmaf(d.z, sc, sh), 0.f));
        sxp[pp][c][XA0(xb + 3)] = make_float2(fmaxf(fmaf(a.w, sc, sh), 0.f), fmaxf(fmaf(d.w, sc, sh), 0.f));
    }
    __syncthreads();

    int pp = tid >> 6, cop = (tid >> 4) & 3, g = tid & 15;
    int co0 = 2 * cop, co1 = 2 * cop + 1;
    u64 acc0[8], acc1[8];
    {
        float b0v = b[co0], b1v = b[co1];
#pragma unroll
        for (int j = 0; j < 8; j++) { acc0[j] = pack2(b0v, b0v); acc1[j] = pack2(b1v, b1v); }
    }

#pragma unroll
    for (int ci = 0; ci < 8; ci++) {
        const u64* wp0 = (const u64*)&swd[(co0 * 8 + ci) * 15];
        const u64* wp1 = (const u64*)&swd[(co1 * 8 + ci) * 15];
        const u64* spg = ((const u64*)&sxp[pp][ci][0]) + 9 * g;
        u64 pe[15];
#pragma unroll
        for (int i = 0; i < 15; i++) pe[i] = spg[XA0(i)];
#pragma unroll
        for (int k = 0; k < 8; k++) {
            u64 w0 = wp0[k], w1 = wp1[k];
#pragma unroll
            for (int j = 0; j < 8; j++) acc0[j] = ffma2(w0, pe[k + j], acc0[j]);
#pragma unroll
            for (int j = 0; j < 8; j++) acc1[j] = ffma2(w1, pe[k + j], acc1[j]);
        }
#pragma unroll
        for (int i = 0; i < 7; i++) pe[i] = pe[i + 8];
#pragma unroll
        for (int i = 7; i < 14; i++) pe[i] = spg[XA0(i + 8)];
#pragma unroll
        for (int k = 8; k < 15; k++) {
            u64 w0 = wp0[k], w1 = wp1[k];
#pragma unroll
            for (int j = 0; j < 8; j++) acc0[j] = ffma2(w0, pe[k - 8 + j], acc0[j]);
#pragma unroll
            for (int j = 0; j < 8; j++) acc1[j] = ffma2(w1, pe[k - 8 + j], acc1[j]);
        }
    }

    int p0 = pbase + pp * 2;
    float f0[8], f1[8], h0[8], h1[8];
    float s0 = 0.f, ss0 = 0.f, s1 = 0.f, ss1 = 0.f;
#pragma unroll
    for (int j = 0; j < 8; j++) {
        unpack2(acc0[j], f0[j], f1[j]);
        unpack2(acc1[j], h0[j], h1[j]);
        s0 += f0[j] + f1[j];  ss0 += f0[j] * f0[j] + f1[j] * f1[j];
        s1 += h0[j] + h1[j];  ss1 += h0[j] * h0[j] + h1[j] * h1[j];
    }
    {
        float4* o = (float4*)&out[p0 * 1024 + co0 * 128 + g * 8];
        o[0] = make_float4(f0[0], f0[1], f0[2], f0[3]);
        o[1] = make_float4(f0[4], f0[5], f0[6], f0[7]);
        o = (float4*)&out[(p0 + 1) * 1024 + co0 * 128 + g * 8];
        o[0] = make_float4(f1[0], f1[1], f1[2], f1[3]);
        o[1] = make_float4(f1[4], f1[5], f1[6], f1[7]);
        o = (float4*)&out[p0 * 1024 + co1 * 128 + g * 8];
        o[0] = make_float4(h0[0], h0[1], h0[2], h0[3]);
        o[1] = make_float4(h0[4], h0[5], h0[6], h0[7]);
        o = (float4*)&out[(p0 + 1) * 1024 + co1 * 128 + g * 8];
        o[0] = make_float4(h1[0], h1[1], h1[2], h1[3]);
        o[1] = make_float4(h1[4], h1[5], h1[6], h1[7]);
    }
    for (int off = 8; off; off >>= 1) {
        s0  += __shfl_down_sync(0xffffffffu, s0,  off, 16);
        ss0 += __shfl_down_sync(0xffffffffu, ss0, off, 16);
        s1  += __shfl_down_sync(0xffffffffu, s1,  off, 16);
        ss1 += __shfl_down_sync(0xffffffffu, ss1, off, 16);
    }
    if (g == 0) {
        atomicAdd(&sred[co0], s0); atomicAdd(&sred[8 + co0], ss0);
        atomicAdd(&sred[co1], s1); atomicAdd(&sred[8 + co1], ss1);
    }
    __syncthreads();
    if (tid < 8) {
        atomicAdd(&g_stats[layer][tid],     (double)sred[tid]);
        atomicAdd(&g_stats[layer][8 + tid], (double)sred[8 + tid]);
    }
}

// ---- conv4: BN3+relu fused; 8->1, K=3, pad=1; float4 loads ----
__global__ void __launch_bounds__(512) k_conv4(const float* __restrict__ w,
                                               const float* __restrict__ b,
                                               const float* __restrict__ gam,
                                               const float* __restrict__ bet) {
    __shared__ float sw[24];
    __shared__ float ssc[8], ssh[8];
    __shared__ float sx[4][8][130];
    __shared__ float sred[32];
    int tid = threadIdx.x;
    int pbase = blockIdx.x * 4;

    if (tid < 24) sw[tid] = w[tid];
    if (tid < 8) {
        double mu  = g_stats[2][tid] / CNT;
        double var = g_stats[2][8 + tid] / CNT - mu * mu;
        float sc = (float)((double)gam[tid] / sqrt(var + 1e-5));
        ssc[tid] = sc;
        ssh[tid] = bet[tid] - (float)mu * sc;
    }
    if (tid >= 448) {
        int i  = tid - 448;
        int lp = i >> 4;
        int c  = (i >> 1) & 7;
        int xi = (i & 1) ? 129 : 0;
        sx[lp][c][xi] = 0.f;
    }
    __syncthreads();

#pragma unroll
    for (int it = 0; it < 2; it++) {
        int i  = tid + it * 512;
        int e4 = i & 31;
        int c  = (i >> 5) & 7;
        int lp = i >> 8;
        float sc = ssc[c], sh = ssh[c];
        float4 a = *(const float4*)&g_actA[(pbase + lp) * 1024 + c * 128 + e4 * 4];
        int xb = e4 * 4 + 1;
        sx[lp][c][xb + 0] = fmaxf(fmaf(a.x, sc, sh), 0.f);
        sx[lp][c][xb + 1] = fmaxf(fmaf(a.y, sc, sh), 0.f);
        sx[lp][c][xb + 2] = fmaxf(fmaf(a.z, sc, sh), 0.f);
        sx[lp][c][xb + 3] = fmaxf(fmaf(a.w, sc, sh), 0.f);
    }
    __syncthreads();

    int lp = tid >> 7, e = tid & 127;
    float acc = b[0];
#pragma unroll
    for (int ci = 0; ci < 8; ci++)
#pragma unroll
        for (int k = 0; k < 3; k++)
            acc = fmaf(sw[ci * 3 + k], sx[lp][ci][e + k], acc);

    g_wraw[(pbase + lp) * 128 + e] = acc;

    float s = acc, ss = acc * acc;
    for (int off = 16; off; off >>= 1) {
        s  += __shfl_down_sync(0xffffffffu, s,  off);
        ss += __shfl_down_sync(0xffffffffu, ss, off);
    }
    int lane = tid & 31, wix = tid >> 5;
    if (lane == 0) { sred[wix] = s; sred[16 + wix] = ss; }
    __syncthreads();
    if (tid == 0) {
        float S = 0.f, SS = 0.f;
        for (int i = 0; i < 16; i++) { S += sred[i]; SS += sred[16 + i]; }
        atomicAdd(&g_stats[3][0], (double)S);
        atomicAdd(&g_stats[3][1], (double)SS);
    }
}

// ---- BN4+relu+weight-sum+compound+dB; 4 pixels per 512-thread block ----
__global__ void __launch_bounds__(512) k_final(const float* __restrict__ gam,
                                               const float* __restrict__ bet) {
    int tid = threadIdx.x;
    int lp = tid >> 7, e = tid & 127;
    int p = blockIdx.x * 4 + lp;
    double mu  = g_stats[3][0] / CNT;
    double var = g_stats[3][1] / CNT - mu * mu;
    float sc = (float)((double)gam[0] / sqrt(var + 1e-5));
    float sh = bet[0] - (float)mu * sc;
    float wv = fmaxf(fmaf(g_wraw[p * 128 + e], sc, sh), 0.f);
    for (int off = 16; off; off >>= 1) wv += __shfl_down_sync(0xffffffffu, wv, off);
    __shared__ float sm[4][4];
    int lane = e & 31, w = e >> 5;
    if (lane == 0) sm[lp][w] = wv;
    __syncthreads();
    if (e == 0) {
        float sW = sm[lp][0] + sm[lp][1] + sm[lp][2] + sm[lp][3];
        float cI = sW * g_sumI[p] * (1.0f / 128.0f);
        float cQ = sW * g_sumQ[p] * (1.0f / 128.0f);
        float mag = sqrtf(cI * cI + cQ * cQ);
        g_ydb[p] = 20.0f * log10f(mag + 1e-20f);
    }
}

__global__ void k_max() {
    float m = -CUDART_INF_F;
    for (int i = blockIdx.x * blockDim.x + threadIdx.x; i < NPIX; i += gridDim.x * blockDim.x)
        m = fmaxf(m, g_ydb[i]);
    for (int off = 16; off; off >>= 1) m = fmaxf(m, __shfl_down_sync(0xffffffffu, m, off));
    __shared__ float sm[8];
    int lane = threadIdx.x & 31, w = threadIdx.x >> 5;
    if (lane == 0) sm[w] = m;
    __syncthreads();
    if (threadIdx.x == 0) {
        float mm = sm[0];
        for (int i = 1; i < (int)(blockDim.x >> 5); i++) mm = fmaxf(mm, sm[i]);
        atomicMax(&g_maxydb, ford(mm));
    }
}

__global__ void k_sub(float* __restrict__ out) {
    int i = blockIdx.x * blockDim.x + threadIdx.x;
    unsigned u = g_maxydb;
    float mx = (u & 0x80000000u) ? __uint_as_float(u & 0x7fffffffu) : __uint_as_float(~u);
    if (i < NPIX) out[i] = g_ydb[i] - mx;
}

extern "C" void kernel_launch(void* const* d_in, const int* in_sizes, int n_in,
                              void* d_out, int out_size) {
    const float* idata     = (const float*)d_in[0];
    const float* qdata     = (const float*)d_in[1];
    const float* angles    = (const float*)d_in[2];
    const float* ele_pos   = (const float*)d_in[3];
    const float* time_zero = (const float*)d_in[4];
    const float* grid      = (const float*)d_in[5];
    const float* w1 = (const float*)d_in[6],  *b1 = (const float*)d_in[7];
    const float* g1 = (const float*)d_in[8],  *be1 = (const float*)d_in[9];
    const float* w2 = (const float*)d_in[10], *b2 = (const float*)d_in[11];
    const float* g2 = (const float*)d_in[12], *be2 = (const float*)d_in[13];
    const float* w3 = (const float*)d_in[14], *b3 = (const float*)d_in[15];
    const float* g3 = (const float*)d_in[16], *be3 = (const float*)d_in[17];
    const float* w4 = (const float*)d_in[18], *b4 = (const float*)d_in[19];
    const float* g4 = (const float*)d_in[20], *be4 = (const float*)d_in[21];
    float* out = (float*)d_out;

    {
        dim3 bl(32, 32), gr(NE / 32, NS / 32);
        k_tr<<<gr, bl>>>(idata, qdata);   // transpose + global init
    }
    k_nrm<<<(NTOT / 16) / 256, 256>>>(idata, qdata);   // 1024 blocks, exact cover
    k_bfconv1<<<NPIX / 4, 256>>>(angles, ele_pos, time_zero, grid, w1, b1);
    k_conv23<<<NPIX / 8, 256>>>(w2, b2, g1, be1, 1, 0);  // BN1; in A -> out B
    k_conv23<<<NPIX / 8, 256>>>(w3, b3, g2, be2, 2, 1);  // BN2; in B -> out A
    k_conv4 <<<NPIX / 4, 512>>>(w4, b4, g3, be3);        // BN3; in A -> wraw
    k_final<<<NPIX / 4, 512>>>(g4, be4);
    k_max<<<64, 256>>>();
    k_sub<<<NPIX / 256, 256>>>(out);
}